// round 8
// baseline (speedup 1.0000x reference)
#include <cuda_runtime.h>
#include <cuda_bf16.h>
#include <math.h>

#define IMG_H 2048
#define IMG_W 4096
#define IMG_C 3
#define ROW_BYTES (IMG_W * IMG_C * 4)

#define BX 64
#define BY 4
#define NTHREADS (BX * BY)
#define PX_PER_THREAD 4   // vertical quad

// Precomputed separable tables.
__device__ float g_bx[IMG_W * 3];    // x-axis control weights
__device__ float g_rdy[IMG_H * 3];   // 5 * sum_y wy3[y]*D[0][y][x]
__device__ float g_rdx[IMG_H * 3];   // 5 * sum_y wy3[y]*D[1][y][x]

__device__ __forceinline__ float cubic_w(float t) {
    float at  = fabsf(t);
    float at2 = at * at;
    float at3 = at2 * at;
    const float a = -0.5f;
    float w_inner = (a + 2.0f) * at3 - (a + 3.0f) * at2 + 1.0f;
    float w_outer = a * at3 - 5.0f * a * at2 + 8.0f * a * at - 4.0f * a;
    return (at <= 1.0f) ? w_inner : ((at < 2.0f) ? w_outer : 0.0f);
}

__device__ __forceinline__ void ctrl_weights3(int i, float inv_scale, float w3[3]) {
    w3[0] = 0.0f; w3[1] = 0.0f; w3[2] = 0.0f;
    float u  = (float)i * inv_scale;
    int   i0 = (int)floorf(u);
    #pragma unroll
    for (int a = -1; a < 3; a++) {
        int   tap = i0 + a;
        float wv  = cubic_w(u - (float)tap);
        int   tc  = min(max(tap, 0), 2);
        w3[tc] += wv;
    }
}

__global__ void setup_tables(const float* __restrict__ dispc) {
    int i = blockIdx.x * blockDim.x + threadIdx.x;
    if (i < IMG_W) {
        float w3[3];
        ctrl_weights3(i, 2.0f / (float)(IMG_W - 1), w3);
        g_bx[i * 3 + 0] = w3[0];
        g_bx[i * 3 + 1] = w3[1];
        g_bx[i * 3 + 2] = w3[2];
    }
    if (i < IMG_H) {
        float w3[3];
        ctrl_weights3(i, 2.0f / (float)(IMG_H - 1), w3);
        #pragma unroll
        for (int x = 0; x < 3; x++) {
            float ry = w3[0] * dispc[0 * 3 + x] + w3[1] * dispc[3 + x] + w3[2] * dispc[6 + x];
            float rx = w3[0] * dispc[9 + x]     + w3[1] * dispc[12 + x] + w3[2] * dispc[15 + x];
            g_rdy[i * 3 + x] = 5.0f * ry;
            g_rdx[i * 3 + x] = 5.0f * rx;
        }
    }
}

// Closed-form Keys (a=-0.5) tap weights for frac t in [0,1).
__device__ __forceinline__ void keys_weights(float t, float w[4]) {
    float s  = 1.0f - t;
    float tt = t * t;
    float ss = s * s;
    w[0] = -0.5f * t * ss;
    w[1] = fmaf(fmaf(1.5f, t, -2.5f), tt, 1.0f);
    w[2] = fmaf(fmaf(1.5f, s, -2.5f), ss, 1.0f);
    w[3] = -0.5f * tt * s;
}

// Single Keys tap weight, tap index K compile-time. Identical expressions to
// keys_weights (bit-exact match with prior rounds).
template<int K>
__device__ __forceinline__ float keys_w1(float t) {
    if (K == 0) { float s = 1.0f - t; return -0.5f * t * (s * s); }
    if (K == 1) { float tt = t * t; return fmaf(fmaf(1.5f, t, -2.5f), tt, 1.0f); }
    if (K == 2) { float s = 1.0f - t; float ss = s * s; return fmaf(fmaf(1.5f, s, -2.5f), ss, 1.0f); }
    { float s = 1.0f - t; return -0.5f * (t * t) * s; }
}

// Rare path: full per-pixel recompute + clamped gather + store for the quad.
__device__ __noinline__ void quad_fallback(const float* __restrict__ img,
                                           float* __restrict__ out,
                                           int w, int h0,
                                           float bx0, float bx1, float bx2) {
    const char* ibase = (const char*)img;
    for (int p = 0; p < PX_PER_THREAD; p++) {
        int h = h0 + p;
        float dy = g_rdy[h * 3 + 0] * bx0 + g_rdy[h * 3 + 1] * bx1 + g_rdy[h * 3 + 2] * bx2;
        float dx = g_rdx[h * 3 + 0] * bx0 + g_rdx[h * 3 + 1] * bx1 + g_rdx[h * 3 + 2] * bx2;
        float yy = (float)h + dy;
        float xx = (float)w + dx;
        float iy0f = floorf(yy), ix0f = floorf(xx);
        int   iy0 = (int)iy0f,   ix0 = (int)ix0f;
        float wy[4], wx[4];
        keys_weights(yy - iy0f, wy);
        keys_weights(xx - ix0f, wx);

        int coff[4];
        #pragma unroll
        for (int b = 0; b < 4; b++) {
            int tx = min(max(ix0 + b - 1, 0), IMG_W - 1);
            coff[b] = tx * (IMG_C * 4);
        }
        float acc0 = 0.0f, acc1 = 0.0f, acc2 = 0.0f;
        #pragma unroll
        for (int a = 0; a < 4; a++) {
            int ty = min(max(iy0 + a - 1, 0), IMG_H - 1);
            const char* rowp = ibase + (unsigned)ty * ROW_BYTES;
            float r0 = 0.0f, r1 = 0.0f, r2 = 0.0f;
            #pragma unroll
            for (int b = 0; b < 4; b++) {
                const float* pp = (const float*)(rowp + coff[b]);
                float wv = wx[b];
                r0 = fmaf(wv, __ldg(pp + 0), r0);
                r1 = fmaf(wv, __ldg(pp + 1), r1);
                r2 = fmaf(wv, __ldg(pp + 2), r2);
            }
            acc0 = fmaf(wy[a], r0, acc0);
            acc1 = fmaf(wy[a], r1, acc1);
            acc2 = fmaf(wy[a], r2, acc2);
        }
        size_t o = ((size_t)h * IMG_W + (size_t)w) * IMG_C;
        out[o + 0] = acc0;
        out[o + 1] = acc1;
        out[o + 2] = acc2;
    }
}

__global__ __launch_bounds__(NTHREADS, 5)
void elastic_warp_kernel(const float* __restrict__ img,
                         float* __restrict__ out) {
    int w  = blockIdx.x * BX + threadIdx.x;
    int h0 = (blockIdx.y * BY + threadIdx.y) * PX_PER_THREAD;

    float bx0 = g_bx[w * 3 + 0], bx1 = g_bx[w * 3 + 1], bx2 = g_bx[w * 3 + 2];

    float fy[4], fx[4];
    int iy00 = 0, ix00 = 0;
    bool fast = true;
    #pragma unroll
    for (int p = 0; p < PX_PER_THREAD; p++) {
        int h = h0 + p;
        float dy = g_rdy[h * 3 + 0] * bx0 + g_rdy[h * 3 + 1] * bx1 + g_rdy[h * 3 + 2] * bx2;
        float dx = g_rdx[h * 3 + 0] * bx0 + g_rdx[h * 3 + 1] * bx1 + g_rdx[h * 3 + 2] * bx2;
        float yy = (float)h + dy;
        float xx = (float)w + dx;
        float iy0f = floorf(yy), ix0f = floorf(xx);
        int   iy0 = (int)iy0f,   ix0 = (int)ix0f;
        fy[p] = yy - iy0f;
        fx[p] = xx - ix0f;
        if (p == 0) { iy00 = iy0; ix00 = ix0; }
        else        { fast = fast && (ix0 == ix00) && (iy0 == iy00 + p); }
    }

    if (!fast) {
        quad_fallback(img, out, w, h0, bx0, bx1, bx2);
        return;
    }

    // Only wx materialized (16 regs); wy computed lazily at use sites.
    float wx[4][4];
    #pragma unroll
    for (int p = 0; p < PX_PER_THREAD; p++)
        keys_weights(fx[p], wx[p]);

    float acc[4][3];
    #pragma unroll
    for (int p = 0; p < PX_PER_THREAD; p++)
        acc[p][0] = acc[p][1] = acc[p][2] = 0.0f;

    const char* ibase = (const char*)img;
    int coff[4];
    #pragma unroll
    for (int b = 0; b < 4; b++) {
        int tx = min(max(ix00 + b - 1, 0), IMG_W - 1);
        coff[b] = tx * (IMG_C * 4);
    }

    size_t obase = ((size_t)h0 * IMG_W + (size_t)w) * IMG_C;

    #pragma unroll
    for (int a = 0; a < 7; a++) {
        int ty = min(max(iy00 + a - 1, 0), IMG_H - 1);
        const char* rowp = ibase + (unsigned)ty * ROW_BYTES;
        float v[12];
        #pragma unroll
        for (int b = 0; b < 4; b++) {
            const float* p = (const float*)(rowp + coff[b]);
            v[b * 3 + 0] = __ldg(p + 0);
            v[b * 3 + 1] = __ldg(p + 1);
            v[b * 3 + 2] = __ldg(p + 2);
        }
        // Pixel p uses row a as tap k = a - p when 0 <= k < 4.
        #pragma unroll
        for (int p = 0; p < PX_PER_THREAD; p++) {
            constexpr int unused = 0; (void)unused;
            int k = a - p;
            if (k >= 0 && k < 4) {
                const float* wxp = wx[p];
                float r0 = wxp[0] * v[0];
                float r1 = wxp[0] * v[1];
                float r2 = wxp[0] * v[2];
                r0 = fmaf(wxp[1], v[3], r0);
                r1 = fmaf(wxp[1], v[4], r1);
                r2 = fmaf(wxp[1], v[5], r2);
                r0 = fmaf(wxp[2], v[6], r0);
                r1 = fmaf(wxp[2], v[7], r1);
                r2 = fmaf(wxp[2], v[8], r2);
                r0 = fmaf(wxp[3], v[9], r0);
                r1 = fmaf(wxp[3], v[10], r1);
                r2 = fmaf(wxp[3], v[11], r2);
                // Lazy wy: k is compile-time under full unroll.
                float wk = (k == 0) ? keys_w1<0>(fy[p])
                         : (k == 1) ? keys_w1<1>(fy[p])
                         : (k == 2) ? keys_w1<2>(fy[p])
                                    : keys_w1<3>(fy[p]);
                acc[p][0] = fmaf(wk, r0, acc[p][0]);
                acc[p][1] = fmaf(wk, r1, acc[p][1]);
                acc[p][2] = fmaf(wk, r2, acc[p][2]);
                // Pixel complete at its last tap: store and free accumulators.
                if (k == 3) {
                    size_t o = obase + (size_t)p * (IMG_W * IMG_C);
                    out[o + 0] = acc[p][0];
                    out[o + 1] = acc[p][1];
                    out[o + 2] = acc[p][2];
                }
            }
        }
    }
}

extern "C" void kernel_launch(void* const* d_in, const int* in_sizes, int n_in,
                              void* d_out, int out_size) {
    const float* img   = (const float*)d_in[0];   // (2048, 4096, 3) fp32
    const float* dispc = (const float*)d_in[1];   // (2, 3, 3) fp32
    float*       out   = (float*)d_out;

    setup_tables<<<(IMG_W + 255) / 256, 256>>>(dispc);

    dim3 block(BX, BY, 1);
    dim3 grid(IMG_W / BX, IMG_H / (BY * PX_PER_THREAD), 1);
    elastic_warp_kernel<<<grid, block>>>(img, out);
}

// round 9
// speedup vs baseline: 1.1246x; 1.1246x over previous
#include <cuda_runtime.h>
#include <cuda_bf16.h>
#include <math.h>

#define IMG_H 2048
#define IMG_W 4096
#define IMG_C 3
#define ROW_BYTES (IMG_W * IMG_C * 4)
#define ROW_F4 (IMG_W * IMG_C / 4)          // 3072
#define TOTAL_F4 (IMG_H * ROW_F4)

#define BX 64
#define BY 4
#define NTHREADS (BX * BY)
#define WARPS_PER_BLOCK (NTHREADS / 32)
#define PX_PER_THREAD 4

#define TROWS 9
#define TPITCH 132                           // floats per staged row (128 + pad)
#define TILE_F (TROWS * TPITCH)              // 1188 floats / warp

// Precomputed separable tables.
__device__ float g_bx[IMG_W * 3];
__device__ float g_rdy[IMG_H * 3];
__device__ float g_rdx[IMG_H * 3];

__device__ __forceinline__ float cubic_w(float t) {
    float at  = fabsf(t);
    float at2 = at * at;
    float at3 = at2 * at;
    const float a = -0.5f;
    float w_inner = (a + 2.0f) * at3 - (a + 3.0f) * at2 + 1.0f;
    float w_outer = a * at3 - 5.0f * a * at2 + 8.0f * a * at - 4.0f * a;
    return (at <= 1.0f) ? w_inner : ((at < 2.0f) ? w_outer : 0.0f);
}

__device__ __forceinline__ void ctrl_weights3(int i, float inv_scale, float w3[3]) {
    w3[0] = 0.0f; w3[1] = 0.0f; w3[2] = 0.0f;
    float u  = (float)i * inv_scale;
    int   i0 = (int)floorf(u);
    #pragma unroll
    for (int a = -1; a < 3; a++) {
        int   tap = i0 + a;
        float wv  = cubic_w(u - (float)tap);
        int   tc  = min(max(tap, 0), 2);
        w3[tc] += wv;
    }
}

__global__ void setup_tables(const float* __restrict__ dispc) {
    int i = blockIdx.x * blockDim.x + threadIdx.x;
    if (i < IMG_W) {
        float w3[3];
        ctrl_weights3(i, 2.0f / (float)(IMG_W - 1), w3);
        g_bx[i * 3 + 0] = w3[0];
        g_bx[i * 3 + 1] = w3[1];
        g_bx[i * 3 + 2] = w3[2];
    }
    if (i < IMG_H) {
        float w3[3];
        ctrl_weights3(i, 2.0f / (float)(IMG_H - 1), w3);
        #pragma unroll
        for (int x = 0; x < 3; x++) {
            float ry = w3[0] * dispc[0 * 3 + x] + w3[1] * dispc[3 + x] + w3[2] * dispc[6 + x];
            float rx = w3[0] * dispc[9 + x]     + w3[1] * dispc[12 + x] + w3[2] * dispc[15 + x];
            g_rdy[i * 3 + x] = 5.0f * ry;
            g_rdx[i * 3 + x] = 5.0f * rx;
        }
    }
}

__device__ __forceinline__ void keys_weights(float t, float w[4]) {
    float s  = 1.0f - t;
    float tt = t * t;
    float ss = s * s;
    w[0] = -0.5f * t * ss;
    w[1] = fmaf(fmaf(1.5f, t, -2.5f), tt, 1.0f);
    w[2] = fmaf(fmaf(1.5f, s, -2.5f), ss, 1.0f);
    w[3] = -0.5f * tt * s;
}

template<int K>
__device__ __forceinline__ float keys_w1(float t) {
    if (K == 0) { float s = 1.0f - t; return -0.5f * t * (s * s); }
    if (K == 1) { float tt = t * t; return fmaf(fmaf(1.5f, t, -2.5f), tt, 1.0f); }
    if (K == 2) { float s = 1.0f - t; float ss = s * s; return fmaf(fmaf(1.5f, s, -2.5f), ss, 1.0f); }
    { float s = 1.0f - t; return -0.5f * (t * t) * s; }
}

// Rare path: per-pixel recompute + clamped global gather + store for the quad.
__device__ __noinline__ void quad_fallback(const float* __restrict__ img,
                                           float* __restrict__ out,
                                           int w, int h0,
                                           float bx0, float bx1, float bx2) {
    const char* ibase = (const char*)img;
    for (int p = 0; p < PX_PER_THREAD; p++) {
        int h = h0 + p;
        float dy = g_rdy[h * 3 + 0] * bx0 + g_rdy[h * 3 + 1] * bx1 + g_rdy[h * 3 + 2] * bx2;
        float dx = g_rdx[h * 3 + 0] * bx0 + g_rdx[h * 3 + 1] * bx1 + g_rdx[h * 3 + 2] * bx2;
        float yy = (float)h + dy;
        float xx = (float)w + dx;
        float iy0f = floorf(yy), ix0f = floorf(xx);
        int   iy0 = (int)iy0f,   ix0 = (int)ix0f;
        float wy[4], wx[4];
        keys_weights(yy - iy0f, wy);
        keys_weights(xx - ix0f, wx);

        int coff[4];
        #pragma unroll
        for (int b = 0; b < 4; b++) {
            int tx = min(max(ix0 + b - 1, 0), IMG_W - 1);
            coff[b] = tx * (IMG_C * 4);
        }
        float acc0 = 0.0f, acc1 = 0.0f, acc2 = 0.0f;
        #pragma unroll
        for (int a = 0; a < 4; a++) {
            int ty = min(max(iy0 + a - 1, 0), IMG_H - 1);
            const char* rowp = ibase + (unsigned)ty * ROW_BYTES;
            float r0 = 0.0f, r1 = 0.0f, r2 = 0.0f;
            #pragma unroll
            for (int b = 0; b < 4; b++) {
                const float* pp = (const float*)(rowp + coff[b]);
                float wv = wx[b];
                r0 = fmaf(wv, __ldg(pp + 0), r0);
                r1 = fmaf(wv, __ldg(pp + 1), r1);
                r2 = fmaf(wv, __ldg(pp + 2), r2);
            }
            acc0 = fmaf(wy[a], r0, acc0);
            acc1 = fmaf(wy[a], r1, acc1);
            acc2 = fmaf(wy[a], r2, acc2);
        }
        size_t o = ((size_t)h * IMG_W + (size_t)w) * IMG_C;
        out[o + 0] = acc0;
        out[o + 1] = acc1;
        out[o + 2] = acc2;
    }
}

__global__ __launch_bounds__(NTHREADS, 4)
void elastic_warp_kernel(const float* __restrict__ img,
                         float* __restrict__ out) {
    __shared__ float tile[WARPS_PER_BLOCK * TILE_F];   // 38016 B

    int w    = blockIdx.x * BX + threadIdx.x;
    int h0   = (blockIdx.y * BY + threadIdx.y) * PX_PER_THREAD;
    int tid  = threadIdx.y * BX + threadIdx.x;
    int lane = tid & 31;
    int wid  = tid >> 5;

    float bx0 = g_bx[w * 3 + 0], bx1 = g_bx[w * 3 + 1], bx2 = g_bx[w * 3 + 2];

    float fy[4], fx[4];
    int iy00 = 0, ix00 = 0;
    bool fast = true;
    #pragma unroll
    for (int p = 0; p < PX_PER_THREAD; p++) {
        int h = h0 + p;
        float dy = g_rdy[h * 3 + 0] * bx0 + g_rdy[h * 3 + 1] * bx1 + g_rdy[h * 3 + 2] * bx2;
        float dx = g_rdx[h * 3 + 0] * bx0 + g_rdx[h * 3 + 1] * bx1 + g_rdx[h * 3 + 2] * bx2;
        float yy = (float)h + dy;
        float xx = (float)w + dx;
        float iy0f = floorf(yy), ix0f = floorf(xx);
        int   iy0 = (int)iy0f,   ix0 = (int)ix0f;
        fy[p] = yy - iy0f;
        fx[p] = xx - ix0f;
        if (p == 0) { iy00 = iy0; ix00 = ix0; }
        else        { fast = fast && (ix0 == ix00) && (iy0 == iy00 + p); }
    }

    // Warp-uniform window + pattern decision.
    int rmin = __reduce_min_sync(0xffffffffu, iy00);
    int rmax = __reduce_max_sync(0xffffffffu, iy00);
    int cmin = __reduce_min_sync(0xffffffffu, ix00);
    int cmax = __reduce_max_sync(0xffffffffu, ix00);
    bool warp_fast = __all_sync(0xffffffffu, fast) &&
                     (rmax - rmin <= 2) && (cmax - cmin <= 36);

    if (!warp_fast) {
        quad_fallback(img, out, w, h0, bx0, bx1, bx2);
        return;
    }

    int row_lo = max(rmin - 1, 0);
    int col_lo = max(cmin - 1, 0) & ~3;          // 16B-aligned float window start
    float* wt  = &tile[wid * TILE_F];

    // Stage 9 rows x 128 floats: one coalesced LDG.128 + STS.128 per row.
    {
        const float4* img4 = (const float4*)img;
        int base4 = (col_lo * 3) >> 2;           // integral, 16B-aligned
        #pragma unroll
        for (int r = 0; r < TROWS; r++) {
            int gr   = min(row_lo + r, IMG_H - 1);
            int idx4 = min(gr * ROW_F4 + base4 + lane, TOTAL_F4 - 1);
            float4 v = __ldg(img4 + idx4);
            *(float4*)(wt + r * TPITCH + lane * 4) = v;
        }
    }
    __syncwarp();

    float wx[4][4];
    #pragma unroll
    for (int p = 0; p < PX_PER_THREAD; p++)
        keys_weights(fx[p], wx[p]);

    float acc[4][3];
    #pragma unroll
    for (int p = 0; p < PX_PER_THREAD; p++)
        acc[p][0] = acc[p][1] = acc[p][2] = 0.0f;

    // Smem tap offsets (clamped; staged window covers all clamped taps).
    int sc[4];
    #pragma unroll
    for (int b = 0; b < 4; b++) {
        int tx = min(max(ix00 + b - 1, 0), IMG_W - 1);
        sc[b] = (tx - col_lo) * 3;
    }

    #pragma unroll
    for (int a = 0; a < 7; a++) {
        int ty = min(max(iy00 + a - 1, 0), IMG_H - 1);
        const float* rowp = wt + (ty - row_lo) * TPITCH;
        float v[12];
        #pragma unroll
        for (int b = 0; b < 4; b++) {
            const float* p = rowp + sc[b];
            v[b * 3 + 0] = p[0];
            v[b * 3 + 1] = p[1];
            v[b * 3 + 2] = p[2];
        }
        #pragma unroll
        for (int p = 0; p < PX_PER_THREAD; p++) {
            int k = a - p;
            if (k >= 0 && k < 4) {
                const float* wxp = wx[p];
                float r0 = wxp[0] * v[0];
                float r1 = wxp[0] * v[1];
                float r2 = wxp[0] * v[2];
                r0 = fmaf(wxp[1], v[3], r0);
                r1 = fmaf(wxp[1], v[4], r1);
                r2 = fmaf(wxp[1], v[5], r2);
                r0 = fmaf(wxp[2], v[6], r0);
                r1 = fmaf(wxp[2], v[7], r1);
                r2 = fmaf(wxp[2], v[8], r2);
                r0 = fmaf(wxp[3], v[9], r0);
                r1 = fmaf(wxp[3], v[10], r1);
                r2 = fmaf(wxp[3], v[11], r2);
                float wk = (k == 0) ? keys_w1<0>(fy[p])
                         : (k == 1) ? keys_w1<1>(fy[p])
                         : (k == 2) ? keys_w1<2>(fy[p])
                                    : keys_w1<3>(fy[p]);
                acc[p][0] = fmaf(wk, r0, acc[p][0]);
                acc[p][1] = fmaf(wk, r1, acc[p][1]);
                acc[p][2] = fmaf(wk, r2, acc[p][2]);
            }
        }
    }

    #pragma unroll
    for (int p = 0; p < PX_PER_THREAD; p++) {
        size_t o = ((size_t)(h0 + p) * IMG_W + (size_t)w) * IMG_C;
        out[o + 0] = acc[p][0];
        out[o + 1] = acc[p][1];
        out[o + 2] = acc[p][2];
    }
}

extern "C" void kernel_launch(void* const* d_in, const int* in_sizes, int n_in,
                              void* d_out, int out_size) {
    const float* img   = (const float*)d_in[0];   // (2048, 4096, 3) fp32
    const float* dispc = (const float*)d_in[1];   // (2, 3, 3) fp32
    float*       out   = (float*)d_out;

    setup_tables<<<(IMG_W + 255) / 256, 256>>>(dispc);

    dim3 block(BX, BY, 1);
    dim3 grid(IMG_W / BX, IMG_H / (BY * PX_PER_THREAD), 1);
    elastic_warp_kernel<<<grid, block>>>(img, out);
}

// round 10
// speedup vs baseline: 1.1583x; 1.0300x over previous
#include <cuda_runtime.h>
#include <cuda_bf16.h>
#include <math.h>
#include <cstdint>

#define IMG_H 2048
#define IMG_W 4096
#define IMG_C 3
#define ROW_BYTES (IMG_W * IMG_C * 4)

#define BX 64
#define BY 4
#define NTHREADS (BX * BY)
#define WARPS_PER_BLOCK (NTHREADS / 32)
#define PX_PER_THREAD 4

#define TROWS 9
#define TPITCH 132                           // floats per staged row = 528 B (16B mult)
#define TROW_BYTES (TPITCH * 4)              // 528
#define TILE_F (TROWS * TPITCH)
#define STAGE_BYTES (TROWS * TROW_BYTES)     // 4752
// col_lo cap so a 528B row copy stays inside the image row:
// col_lo*12 + 528 <= 49152  ->  col_lo <= 4052
#define COL_LO_MAX 4052

// Precomputed separable tables.
__device__ float g_bx[IMG_W * 3];
__device__ float g_rdy[IMG_H * 3];
__device__ float g_rdx[IMG_H * 3];

__device__ __forceinline__ uint32_t smem_u32(const void* p) {
    uint32_t a;
    asm("{ .reg .u64 t; cvta.to.shared.u64 t, %1; cvt.u32.u64 %0, t; }" : "=r"(a) : "l"(p));
    return a;
}

__device__ __forceinline__ float cubic_w(float t) {
    float at  = fabsf(t);
    float at2 = at * at;
    float at3 = at2 * at;
    const float a = -0.5f;
    float w_inner = (a + 2.0f) * at3 - (a + 3.0f) * at2 + 1.0f;
    float w_outer = a * at3 - 5.0f * a * at2 + 8.0f * a * at - 4.0f * a;
    return (at <= 1.0f) ? w_inner : ((at < 2.0f) ? w_outer : 0.0f);
}

__device__ __forceinline__ void ctrl_weights3(int i, float inv_scale, float w3[3]) {
    w3[0] = 0.0f; w3[1] = 0.0f; w3[2] = 0.0f;
    float u  = (float)i * inv_scale;
    int   i0 = (int)floorf(u);
    #pragma unroll
    for (int a = -1; a < 3; a++) {
        int   tap = i0 + a;
        float wv  = cubic_w(u - (float)tap);
        int   tc  = min(max(tap, 0), 2);
        w3[tc] += wv;
    }
}

__global__ void setup_tables(const float* __restrict__ dispc) {
    int i = blockIdx.x * blockDim.x + threadIdx.x;
    if (i < IMG_W) {
        float w3[3];
        ctrl_weights3(i, 2.0f / (float)(IMG_W - 1), w3);
        g_bx[i * 3 + 0] = w3[0];
        g_bx[i * 3 + 1] = w3[1];
        g_bx[i * 3 + 2] = w3[2];
    }
    if (i < IMG_H) {
        float w3[3];
        ctrl_weights3(i, 2.0f / (float)(IMG_H - 1), w3);
        #pragma unroll
        for (int x = 0; x < 3; x++) {
            float ry = w3[0] * dispc[0 * 3 + x] + w3[1] * dispc[3 + x] + w3[2] * dispc[6 + x];
            float rx = w3[0] * dispc[9 + x]     + w3[1] * dispc[12 + x] + w3[2] * dispc[15 + x];
            g_rdy[i * 3 + x] = 5.0f * ry;
            g_rdx[i * 3 + x] = 5.0f * rx;
        }
    }
}

__device__ __forceinline__ void keys_weights(float t, float w[4]) {
    float s  = 1.0f - t;
    float tt = t * t;
    float ss = s * s;
    w[0] = -0.5f * t * ss;
    w[1] = fmaf(fmaf(1.5f, t, -2.5f), tt, 1.0f);
    w[2] = fmaf(fmaf(1.5f, s, -2.5f), ss, 1.0f);
    w[3] = -0.5f * tt * s;
}

template<int K>
__device__ __forceinline__ float keys_w1(float t) {
    if (K == 0) { float s = 1.0f - t; return -0.5f * t * (s * s); }
    if (K == 1) { float tt = t * t; return fmaf(fmaf(1.5f, t, -2.5f), tt, 1.0f); }
    if (K == 2) { float s = 1.0f - t; float ss = s * s; return fmaf(fmaf(1.5f, s, -2.5f), ss, 1.0f); }
    { float s = 1.0f - t; return -0.5f * (t * t) * s; }
}

// Rare path: per-pixel recompute + clamped global gather + store for the quad.
__device__ __noinline__ void quad_fallback(const float* __restrict__ img,
                                           float* __restrict__ out,
                                           int w, int h0,
                                           float bx0, float bx1, float bx2) {
    const char* ibase = (const char*)img;
    for (int p = 0; p < PX_PER_THREAD; p++) {
        int h = h0 + p;
        float dy = g_rdy[h * 3 + 0] * bx0 + g_rdy[h * 3 + 1] * bx1 + g_rdy[h * 3 + 2] * bx2;
        float dx = g_rdx[h * 3 + 0] * bx0 + g_rdx[h * 3 + 1] * bx1 + g_rdx[h * 3 + 2] * bx2;
        float yy = (float)h + dy;
        float xx = (float)w + dx;
        float iy0f = floorf(yy), ix0f = floorf(xx);
        int   iy0 = (int)iy0f,   ix0 = (int)ix0f;
        float wy[4], wx[4];
        keys_weights(yy - iy0f, wy);
        keys_weights(xx - ix0f, wx);

        int coff[4];
        #pragma unroll
        for (int b = 0; b < 4; b++) {
            int tx = min(max(ix0 + b - 1, 0), IMG_W - 1);
            coff[b] = tx * (IMG_C * 4);
        }
        float acc0 = 0.0f, acc1 = 0.0f, acc2 = 0.0f;
        #pragma unroll
        for (int a = 0; a < 4; a++) {
            int ty = min(max(iy0 + a - 1, 0), IMG_H - 1);
            const char* rowp = ibase + (unsigned)ty * ROW_BYTES;
            float r0 = 0.0f, r1 = 0.0f, r2 = 0.0f;
            #pragma unroll
            for (int b = 0; b < 4; b++) {
                const float* pp = (const float*)(rowp + coff[b]);
                float wv = wx[b];
                r0 = fmaf(wv, __ldg(pp + 0), r0);
                r1 = fmaf(wv, __ldg(pp + 1), r1);
                r2 = fmaf(wv, __ldg(pp + 2), r2);
            }
            acc0 = fmaf(wy[a], r0, acc0);
            acc1 = fmaf(wy[a], r1, acc1);
            acc2 = fmaf(wy[a], r2, acc2);
        }
        size_t o = ((size_t)h * IMG_W + (size_t)w) * IMG_C;
        out[o + 0] = acc0;
        out[o + 1] = acc1;
        out[o + 2] = acc2;
    }
}

__global__ __launch_bounds__(NTHREADS, 4)
void elastic_warp_kernel(const float* __restrict__ img,
                         float* __restrict__ out) {
    __shared__ float    tile[WARPS_PER_BLOCK * TILE_F];   // 38016 B
    __shared__ uint64_t mbar[WARPS_PER_BLOCK];

    int w    = blockIdx.x * BX + threadIdx.x;
    int h0   = (blockIdx.y * BY + threadIdx.y) * PX_PER_THREAD;
    int tid  = threadIdx.y * BX + threadIdx.x;
    int lane = tid & 31;
    int wid  = tid >> 5;

    // Init all per-warp mbarriers once, before any divergence.
    if (tid < WARPS_PER_BLOCK) {
        uint32_t mb = smem_u32(&mbar[tid]);
        asm volatile("mbarrier.init.shared.b64 [%0], 1;" :: "r"(mb) : "memory");
    }
    asm volatile("fence.proxy.async.shared::cta;" ::: "memory");
    __syncthreads();

    float bx0 = g_bx[w * 3 + 0], bx1 = g_bx[w * 3 + 1], bx2 = g_bx[w * 3 + 2];

    float fy[4], fx[4];
    int iy00 = 0, ix00 = 0;
    bool fast = true;
    #pragma unroll
    for (int p = 0; p < PX_PER_THREAD; p++) {
        int h = h0 + p;
        float dy = g_rdy[h * 3 + 0] * bx0 + g_rdy[h * 3 + 1] * bx1 + g_rdy[h * 3 + 2] * bx2;
        float dx = g_rdx[h * 3 + 0] * bx0 + g_rdx[h * 3 + 1] * bx1 + g_rdx[h * 3 + 2] * bx2;
        float yy = (float)h + dy;
        float xx = (float)w + dx;
        float iy0f = floorf(yy), ix0f = floorf(xx);
        int   iy0 = (int)iy0f,   ix0 = (int)ix0f;
        fy[p] = yy - iy0f;
        fx[p] = xx - ix0f;
        if (p == 0) { iy00 = iy0; ix00 = ix0; }
        else        { fast = fast && (ix0 == ix00) && (iy0 == iy00 + p); }
    }

    // Warp-uniform window + pattern decision.
    int rmin = __reduce_min_sync(0xffffffffu, iy00);
    int rmax = __reduce_max_sync(0xffffffffu, iy00);
    int cmin = __reduce_min_sync(0xffffffffu, ix00);
    int cmax = __reduce_max_sync(0xffffffffu, ix00);
    bool warp_fast = __all_sync(0xffffffffu, fast) &&
                     (rmax - rmin <= 2) && (cmax - cmin <= 36);

    if (!warp_fast) {
        quad_fallback(img, out, w, h0, bx0, bx1, bx2);
        return;
    }

    // Window origin, clamped BOTH ways (bounds-safe at all four borders).
    int row_lo = min(max(rmin - 1, 0), IMG_H - 1);
    int col_lo = min(max(cmin - 1, 0) & ~3, COL_LO_MAX);

    float*   wt    = &tile[wid * TILE_F];
    uint32_t wt_u  = smem_u32(wt);
    uint32_t mb_u  = smem_u32(&mbar[wid]);

    // Stage 9 rows x 528B via bulk-copy engine (off the L1 pipe).
    if (lane == 0) {
        asm volatile("mbarrier.arrive.expect_tx.shared.b64 _, [%0], %1;"
                     :: "r"(mb_u), "r"((uint32_t)STAGE_BYTES) : "memory");
        const char* ibase = (const char*)img;
        #pragma unroll
        for (int r = 0; r < TROWS; r++) {
            int gr = min(row_lo + r, IMG_H - 1);
            const char* src = ibase + (unsigned)gr * ROW_BYTES + (unsigned)col_lo * 12u;
            asm volatile("cp.async.bulk.shared::cta.global.mbarrier::complete_tx::bytes "
                         "[%0], [%1], %2, [%3];"
                         :: "r"(wt_u + (uint32_t)(r * TROW_BYTES)), "l"(src),
                            "r"((uint32_t)TROW_BYTES), "r"(mb_u) : "memory");
        }
    }

    // Compute x-weights while the copy flies.
    float wx[4][4];
    #pragma unroll
    for (int p = 0; p < PX_PER_THREAD; p++)
        keys_weights(fx[p], wx[p]);

    float acc[4][3];
    #pragma unroll
    for (int p = 0; p < PX_PER_THREAD; p++)
        acc[p][0] = acc[p][1] = acc[p][2] = 0.0f;

    int sc[4];
    #pragma unroll
    for (int b = 0; b < 4; b++) {
        int tx = min(max(ix00 + b - 1, 0), IMG_W - 1);
        sc[b] = (tx - col_lo) * 3;
    }

    // All lanes wait for the staged tile (acquire).
    {
        uint32_t done;
        asm volatile(
            "{\n\t.reg .pred p;\n\t"
            "mbarrier.try_wait.parity.acquire.cta.shared::cta.b64 p, [%1], 0;\n\t"
            "selp.b32 %0, 1, 0, p;\n\t}"
            : "=r"(done) : "r"(mb_u) : "memory");
        if (!done) {
            asm volatile(
                "{\n\t.reg .pred P1;\n\t"
                "W10_%=:\n\t"
                "mbarrier.try_wait.parity.acquire.cta.shared::cta.b64 P1, [%0], 0, 0x989680;\n\t"
                "@P1 bra.uni D10_%=;\n\t"
                "bra.uni W10_%=;\n\t"
                "D10_%=:\n\t}"
                :: "r"(mb_u) : "memory");
        }
    }

    #pragma unroll
    for (int a = 0; a < 7; a++) {
        int ty = min(max(iy00 + a - 1, 0), IMG_H - 1);
        const float* rowp = wt + (ty - row_lo) * TPITCH;
        float v[12];
        #pragma unroll
        for (int b = 0; b < 4; b++) {
            const float* p = rowp + sc[b];
            v[b * 3 + 0] = p[0];
            v[b * 3 + 1] = p[1];
            v[b * 3 + 2] = p[2];
        }
        #pragma unroll
        for (int p = 0; p < PX_PER_THREAD; p++) {
            int k = a - p;
            if (k >= 0 && k < 4) {
                const float* wxp = wx[p];
                float r0 = wxp[0] * v[0];
                float r1 = wxp[0] * v[1];
                float r2 = wxp[0] * v[2];
                r0 = fmaf(wxp[1], v[3], r0);
                r1 = fmaf(wxp[1], v[4], r1);
                r2 = fmaf(wxp[1], v[5], r2);
                r0 = fmaf(wxp[2], v[6], r0);
                r1 = fmaf(wxp[2], v[7], r1);
                r2 = fmaf(wxp[2], v[8], r2);
                r0 = fmaf(wxp[3], v[9], r0);
                r1 = fmaf(wxp[3], v[10], r1);
                r2 = fmaf(wxp[3], v[11], r2);
                float wk = (k == 0) ? keys_w1<0>(fy[p])
                         : (k == 1) ? keys_w1<1>(fy[p])
                         : (k == 2) ? keys_w1<2>(fy[p])
                                    : keys_w1<3>(fy[p]);
                acc[p][0] = fmaf(wk, r0, acc[p][0]);
                acc[p][1] = fmaf(wk, r1, acc[p][1]);
                acc[p][2] = fmaf(wk, r2, acc[p][2]);
            }
        }
    }

    #pragma unroll
    for (int p = 0; p < PX_PER_THREAD; p++) {
        size_t o = ((size_t)(h0 + p) * IMG_W + (size_t)w) * IMG_C;
        out[o + 0] = acc[p][0];
        out[o + 1] = acc[p][1];
        out[o + 2] = acc[p][2];
    }
}

extern "C" void kernel_launch(void* const* d_in, const int* in_sizes, int n_in,
                              void* d_out, int out_size) {
    const float* img   = (const float*)d_in[0];   // (2048, 4096, 3) fp32
    const float* dispc = (const float*)d_in[1];   // (2, 3, 3) fp32
    float*       out   = (float*)d_out;

    setup_tables<<<(IMG_W + 255) / 256, 256>>>(dispc);

    dim3 block(BX, BY, 1);
    dim3 grid(IMG_W / BX, IMG_H / (BY * PX_PER_THREAD), 1);
    elastic_warp_kernel<<<grid, block>>>(img, out);
}

// round 11
// speedup vs baseline: 1.1896x; 1.0270x over previous
#include <cuda_runtime.h>
#include <cuda_bf16.h>
#include <math.h>
#include <cstdint>

#define IMG_H 2048
#define IMG_W 4096
#define IMG_C 3
#define ROW_BYTES (IMG_W * IMG_C * 4)

#define BX 64
#define BY 4
#define NTHREADS (BX * BY)
#define WARPS_PER_BLOCK (NTHREADS / 32)
#define PX_PER_THREAD 4

#define TROWS 9
#define TPITCH 132                           // floats per staged row = 528 B
#define TROW_BYTES (TPITCH * 4)              // 528
#define TILE_F (TROWS * TPITCH)
#define STAGE_BYTES (TROWS * TROW_BYTES)     // 4752
#define COL_LO_MAX 4052                      // col_lo*12 + 528 <= 49152

// Precomputed separable tables, float4-padded for single wide loads.
__device__ float4 g_bx4[IMG_W];    // (bx0,bx1,bx2,-)
__device__ float4 g_rdy4[IMG_H];   // (rdy0,rdy1,rdy2,-)
__device__ float4 g_rdx4[IMG_H];   // (rdx0,rdx1,rdx2,-)

__device__ __forceinline__ uint32_t smem_u32(const void* p) {
    uint32_t a;
    asm("{ .reg .u64 t; cvta.to.shared.u64 t, %1; cvt.u32.u64 %0, t; }" : "=r"(a) : "l"(p));
    return a;
}

__device__ __forceinline__ float cubic_w(float t) {
    float at  = fabsf(t);
    float at2 = at * at;
    float at3 = at2 * at;
    const float a = -0.5f;
    float w_inner = (a + 2.0f) * at3 - (a + 3.0f) * at2 + 1.0f;
    float w_outer = a * at3 - 5.0f * a * at2 + 8.0f * a * at - 4.0f * a;
    return (at <= 1.0f) ? w_inner : ((at < 2.0f) ? w_outer : 0.0f);
}

__device__ __forceinline__ void ctrl_weights3(int i, float inv_scale, float w3[3]) {
    w3[0] = 0.0f; w3[1] = 0.0f; w3[2] = 0.0f;
    float u  = (float)i * inv_scale;
    int   i0 = (int)floorf(u);
    #pragma unroll
    for (int a = -1; a < 3; a++) {
        int   tap = i0 + a;
        float wv  = cubic_w(u - (float)tap);
        int   tc  = min(max(tap, 0), 2);
        w3[tc] += wv;
    }
}

__global__ void setup_tables(const float* __restrict__ dispc) {
    int i = blockIdx.x * blockDim.x + threadIdx.x;
    if (i < IMG_W) {
        float w3[3];
        ctrl_weights3(i, 2.0f / (float)(IMG_W - 1), w3);
        g_bx4[i] = make_float4(w3[0], w3[1], w3[2], 0.0f);
    }
    if (i < IMG_H) {
        float w3[3];
        ctrl_weights3(i, 2.0f / (float)(IMG_H - 1), w3);
        float ry[3], rx[3];
        #pragma unroll
        for (int x = 0; x < 3; x++) {
            ry[x] = 5.0f * (w3[0] * dispc[0 * 3 + x] + w3[1] * dispc[3 + x] + w3[2] * dispc[6 + x]);
            rx[x] = 5.0f * (w3[0] * dispc[9 + x]     + w3[1] * dispc[12 + x] + w3[2] * dispc[15 + x]);
        }
        g_rdy4[i] = make_float4(ry[0], ry[1], ry[2], 0.0f);
        g_rdx4[i] = make_float4(rx[0], rx[1], rx[2], 0.0f);
    }
}

__device__ __forceinline__ void keys_weights(float t, float w[4]) {
    float s  = 1.0f - t;
    float tt = t * t;
    float ss = s * s;
    w[0] = -0.5f * t * ss;
    w[1] = fmaf(fmaf(1.5f, t, -2.5f), tt, 1.0f);
    w[2] = fmaf(fmaf(1.5f, s, -2.5f), ss, 1.0f);
    w[3] = -0.5f * tt * s;
}

// Rare path: per-pixel recompute + clamped global gather + store for the quad.
__device__ __noinline__ void quad_fallback(const float* __restrict__ img,
                                           float* __restrict__ out,
                                           int w, int h0, float4 bxv) {
    const char* ibase = (const char*)img;
    for (int p = 0; p < PX_PER_THREAD; p++) {
        int h = h0 + p;
        float4 ryv = __ldg(&g_rdy4[h]);
        float4 rxv = __ldg(&g_rdx4[h]);
        float dy = ryv.x * bxv.x + ryv.y * bxv.y + ryv.z * bxv.z;
        float dx = rxv.x * bxv.x + rxv.y * bxv.y + rxv.z * bxv.z;
        float yy = (float)h + dy;
        float xx = (float)w + dx;
        float iy0f = floorf(yy), ix0f = floorf(xx);
        int   iy0 = (int)iy0f,   ix0 = (int)ix0f;
        float wy[4], wx[4];
        keys_weights(yy - iy0f, wy);
        keys_weights(xx - ix0f, wx);

        int coff[4];
        #pragma unroll
        for (int b = 0; b < 4; b++) {
            int tx = min(max(ix0 + b - 1, 0), IMG_W - 1);
            coff[b] = tx * (IMG_C * 4);
        }
        float acc0 = 0.0f, acc1 = 0.0f, acc2 = 0.0f;
        #pragma unroll
        for (int a = 0; a < 4; a++) {
            int ty = min(max(iy0 + a - 1, 0), IMG_H - 1);
            const char* rowp = ibase + (unsigned)ty * ROW_BYTES;
            float r0 = 0.0f, r1 = 0.0f, r2 = 0.0f;
            #pragma unroll
            for (int b = 0; b < 4; b++) {
                const float* pp = (const float*)(rowp + coff[b]);
                float wv = wx[b];
                r0 = fmaf(wv, __ldg(pp + 0), r0);
                r1 = fmaf(wv, __ldg(pp + 1), r1);
                r2 = fmaf(wv, __ldg(pp + 2), r2);
            }
            acc0 = fmaf(wy[a], r0, acc0);
            acc1 = fmaf(wy[a], r1, acc1);
            acc2 = fmaf(wy[a], r2, acc2);
        }
        uint32_t o = ((uint32_t)h * IMG_W + (uint32_t)w) * 12u;
        float* po = (float*)((char*)out + o);
        po[0] = acc0; po[1] = acc1; po[2] = acc2;
    }
}

__global__ __launch_bounds__(NTHREADS, 4)
void elastic_warp_kernel(const float* __restrict__ img,
                         float* __restrict__ out) {
    __shared__ float    tile[WARPS_PER_BLOCK * TILE_F];   // 38016 B
    __shared__ uint64_t mbar[WARPS_PER_BLOCK];

    int w    = blockIdx.x * BX + threadIdx.x;
    int h0   = (blockIdx.y * BY + threadIdx.y) * PX_PER_THREAD;
    int tid  = threadIdx.y * BX + threadIdx.x;
    int lane = tid & 31;
    int wid  = tid >> 5;

    if (tid < WARPS_PER_BLOCK) {
        uint32_t mb = smem_u32(&mbar[tid]);
        asm volatile("mbarrier.init.shared.b64 [%0], 1;" :: "r"(mb) : "memory");
    }
    asm volatile("fence.proxy.async.shared::cta;" ::: "memory");
    __syncthreads();

    float4 bxv = __ldg(&g_bx4[w]);

    float fy[4], fx[4];
    int iy00 = 0, ix00 = 0;
    bool fast = true;
    #pragma unroll
    for (int p = 0; p < PX_PER_THREAD; p++) {
        int h = h0 + p;
        float4 ryv = __ldg(&g_rdy4[h]);
        float4 rxv = __ldg(&g_rdx4[h]);
        float dy = ryv.x * bxv.x + ryv.y * bxv.y + ryv.z * bxv.z;
        float dx = rxv.x * bxv.x + rxv.y * bxv.y + rxv.z * bxv.z;
        float yy = (float)h + dy;
        float xx = (float)w + dx;
        float iy0f = floorf(yy), ix0f = floorf(xx);
        int   iy0 = (int)iy0f,   ix0 = (int)ix0f;
        fy[p] = yy - iy0f;
        fx[p] = xx - ix0f;
        if (p == 0) { iy00 = iy0; ix00 = ix0; }
        else        { fast = fast && (ix0 == ix00) && (iy0 == iy00 + p); }
    }

    int rmin = __reduce_min_sync(0xffffffffu, iy00);
    int rmax = __reduce_max_sync(0xffffffffu, iy00);
    int cmin = __reduce_min_sync(0xffffffffu, ix00);
    int cmax = __reduce_max_sync(0xffffffffu, ix00);
    bool warp_fast = __all_sync(0xffffffffu, fast) &&
                     (rmax - rmin <= 2) && (cmax - cmin <= 36);

    if (!warp_fast) {
        quad_fallback(img, out, w, h0, bxv);
        return;
    }

    int row_lo = min(max(rmin - 1, 0), IMG_H - 1);
    int col_lo = min(max(cmin - 1, 0) & ~3, COL_LO_MAX);

    float*   wt    = &tile[wid * TILE_F];
    uint32_t wt_u  = smem_u32(wt);
    uint32_t mb_u  = smem_u32(&mbar[wid]);

    // Stage 9 rows x 528B via bulk-copy engine (off the L1 pipe).
    if (lane == 0) {
        asm volatile("mbarrier.arrive.expect_tx.shared.b64 _, [%0], %1;"
                     :: "r"(mb_u), "r"((uint32_t)STAGE_BYTES) : "memory");
        const char* ibase = (const char*)img;
        #pragma unroll
        for (int r = 0; r < TROWS; r++) {
            int gr = min(row_lo + r, IMG_H - 1);
            const char* src = ibase + (unsigned)gr * ROW_BYTES + (unsigned)col_lo * 12u;
            asm volatile("cp.async.bulk.shared::cta.global.mbarrier::complete_tx::bytes "
                         "[%0], [%1], %2, [%3];"
                         :: "r"(wt_u + (uint32_t)(r * TROW_BYTES)), "l"(src),
                            "r"((uint32_t)TROW_BYTES), "r"(mb_u) : "memory");
        }
    }

    // Weights, all materialized, while the copy flies.
    float wx[4][4], wy[4][4];
    #pragma unroll
    for (int p = 0; p < PX_PER_THREAD; p++) {
        keys_weights(fx[p], wx[p]);
        keys_weights(fy[p], wy[p]);
    }

    float acc[4][3];
    #pragma unroll
    for (int p = 0; p < PX_PER_THREAD; p++)
        acc[p][0] = acc[p][1] = acc[p][2] = 0.0f;

    int sc[4];
    #pragma unroll
    for (int b = 0; b < 4; b++) {
        int tx = min(max(ix00 + b - 1, 0), IMG_W - 1);
        sc[b] = (tx - col_lo) * 3;
    }

    // Wait for the staged tile (acquire).
    {
        uint32_t done;
        asm volatile(
            "{\n\t.reg .pred p;\n\t"
            "mbarrier.try_wait.parity.acquire.cta.shared::cta.b64 p, [%1], 0;\n\t"
            "selp.b32 %0, 1, 0, p;\n\t}"
            : "=r"(done) : "r"(mb_u) : "memory");
        if (!done) {
            asm volatile(
                "{\n\t.reg .pred P1;\n\t"
                "W11_%=:\n\t"
                "mbarrier.try_wait.parity.acquire.cta.shared::cta.b64 P1, [%0], 0, 0x989680;\n\t"
                "@P1 bra.uni D11_%=;\n\t"
                "bra.uni W11_%=;\n\t"
                "D11_%=:\n\t}"
                :: "r"(mb_u) : "memory");
        }
    }

    #pragma unroll
    for (int a = 0; a < 7; a++) {
        int ty = min(max(iy00 + a - 1, 0), IMG_H - 1);
        const float* rowp = wt + (ty - row_lo) * TPITCH;
        float v[12];
        #pragma unroll
        for (int b = 0; b < 4; b++) {
            const float* p = rowp + sc[b];
            v[b * 3 + 0] = p[0];
            v[b * 3 + 1] = p[1];
            v[b * 3 + 2] = p[2];
        }
        #pragma unroll
        for (int p = 0; p < PX_PER_THREAD; p++) {
            int k = a - p;
            if (k >= 0 && k < 4) {
                const float* wxp = wx[p];
                float r0 = wxp[0] * v[0];
                float r1 = wxp[0] * v[1];
                float r2 = wxp[0] * v[2];
                r0 = fmaf(wxp[1], v[3], r0);
                r1 = fmaf(wxp[1], v[4], r1);
                r2 = fmaf(wxp[1], v[5], r2);
                r0 = fmaf(wxp[2], v[6], r0);
                r1 = fmaf(wxp[2], v[7], r1);
                r2 = fmaf(wxp[2], v[8], r2);
                r0 = fmaf(wxp[3], v[9], r0);
                r1 = fmaf(wxp[3], v[10], r1);
                r2 = fmaf(wxp[3], v[11], r2);
                float wk = wy[p][k];
                acc[p][0] = fmaf(wk, r0, acc[p][0]);
                acc[p][1] = fmaf(wk, r1, acc[p][1]);
                acc[p][2] = fmaf(wk, r2, acc[p][2]);
            }
        }
    }

    uint32_t obase = ((uint32_t)h0 * IMG_W + (uint32_t)w) * 12u;
    #pragma unroll
    for (int p = 0; p < PX_PER_THREAD; p++) {
        float* po = (float*)((char*)out + obase + (uint32_t)p * (IMG_W * 12u));
        po[0] = acc[p][0];
        po[1] = acc[p][1];
        po[2] = acc[p][2];
    }
}

extern "C" void kernel_launch(void* const* d_in, const int* in_sizes, int n_in,
                              void* d_out, int out_size) {
    const float* img   = (const float*)d_in[0];   // (2048, 4096, 3) fp32
    const float* dispc = (const float*)d_in[1];   // (2, 3, 3) fp32
    float*       out   = (float*)d_out;

    setup_tables<<<(IMG_W + 255) / 256, 256>>>(dispc);

    dim3 block(BX, BY, 1);
    dim3 grid(IMG_W / BX, IMG_H / (BY * PX_PER_THREAD), 1);
    elastic_warp_kernel<<<grid, block>>>(img, out);
}

// round 12
// speedup vs baseline: 1.1921x; 1.0021x over previous
#include <cuda_runtime.h>
#include <cuda_bf16.h>
#include <math.h>
#include <cstdint>

#define IMG_H 2048
#define IMG_W 4096
#define IMG_C 3
#define ROW_BYTES (IMG_W * IMG_C * 4)

#define BX 64
#define BY 2
#define NTHREADS (BX * BY)
#define WARPS_PER_BLOCK (NTHREADS / 32)
#define PX 6
#define ROWS_PER_BLOCK (BY * PX)           // 12

#define TROWS 11
#define TPITCH 132                          // floats per staged row = 528 B
#define TROW_BYTES (TPITCH * 4)             // 528
#define TILE_F (TROWS * TPITCH)             // 1452
#define STAGE_BYTES (TROWS * TROW_BYTES)    // 5808
#define COL_LO_MAX 4052                     // col_lo*12 + 528 <= 49152

// Precomputed separable tables, float4-padded.
__device__ float4 g_bx4[IMG_W];
__device__ float4 g_rdy4[IMG_H];
__device__ float4 g_rdx4[IMG_H];

__device__ __forceinline__ uint32_t smem_u32(const void* p) {
    uint32_t a;
    asm("{ .reg .u64 t; cvta.to.shared.u64 t, %1; cvt.u32.u64 %0, t; }" : "=r"(a) : "l"(p));
    return a;
}

__device__ __forceinline__ float cubic_w(float t) {
    float at  = fabsf(t);
    float at2 = at * at;
    float at3 = at2 * at;
    const float a = -0.5f;
    float w_inner = (a + 2.0f) * at3 - (a + 3.0f) * at2 + 1.0f;
    float w_outer = a * at3 - 5.0f * a * at2 + 8.0f * a * at - 4.0f * a;
    return (at <= 1.0f) ? w_inner : ((at < 2.0f) ? w_outer : 0.0f);
}

__device__ __forceinline__ void ctrl_weights3(int i, float inv_scale, float w3[3]) {
    w3[0] = 0.0f; w3[1] = 0.0f; w3[2] = 0.0f;
    float u  = (float)i * inv_scale;
    int   i0 = (int)floorf(u);
    #pragma unroll
    for (int a = -1; a < 3; a++) {
        int   tap = i0 + a;
        float wv  = cubic_w(u - (float)tap);
        int   tc  = min(max(tap, 0), 2);
        w3[tc] += wv;
    }
}

__global__ void setup_tables(const float* __restrict__ dispc) {
    int i = blockIdx.x * blockDim.x + threadIdx.x;
    if (i < IMG_W) {
        float w3[3];
        ctrl_weights3(i, 2.0f / (float)(IMG_W - 1), w3);
        g_bx4[i] = make_float4(w3[0], w3[1], w3[2], 0.0f);
    }
    if (i < IMG_H) {
        float w3[3];
        ctrl_weights3(i, 2.0f / (float)(IMG_H - 1), w3);
        float ry[3], rx[3];
        #pragma unroll
        for (int x = 0; x < 3; x++) {
            ry[x] = 5.0f * (w3[0] * dispc[0 * 3 + x] + w3[1] * dispc[3 + x] + w3[2] * dispc[6 + x]);
            rx[x] = 5.0f * (w3[0] * dispc[9 + x]     + w3[1] * dispc[12 + x] + w3[2] * dispc[15 + x]);
        }
        g_rdy4[i] = make_float4(ry[0], ry[1], ry[2], 0.0f);
        g_rdx4[i] = make_float4(rx[0], rx[1], rx[2], 0.0f);
    }
}

__device__ __forceinline__ void keys_weights(float t, float w[4]) {
    float s  = 1.0f - t;
    float tt = t * t;
    float ss = s * s;
    w[0] = -0.5f * t * ss;
    w[1] = fmaf(fmaf(1.5f, t, -2.5f), tt, 1.0f);
    w[2] = fmaf(fmaf(1.5f, s, -2.5f), ss, 1.0f);
    w[3] = -0.5f * tt * s;
}

// Global per-pixel gather + store, h-guarded. Used for edge warps and
// unstageable warps.
__device__ __noinline__ void global_fallback(const float* __restrict__ img,
                                             float* __restrict__ out,
                                             int w, int h0, float4 bxv) {
    const char* ibase = (const char*)img;
    for (int p = 0; p < PX; p++) {
        int h = h0 + p;
        if (h >= IMG_H) break;
        float4 ryv = __ldg(&g_rdy4[h]);
        float4 rxv = __ldg(&g_rdx4[h]);
        float dy = ryv.x * bxv.x + ryv.y * bxv.y + ryv.z * bxv.z;
        float dx = rxv.x * bxv.x + rxv.y * bxv.y + rxv.z * bxv.z;
        float yy = (float)h + dy;
        float xx = (float)w + dx;
        float iy0f = floorf(yy), ix0f = floorf(xx);
        int   iy0 = (int)iy0f,   ix0 = (int)ix0f;
        float wy[4], wx[4];
        keys_weights(yy - iy0f, wy);
        keys_weights(xx - ix0f, wx);

        int coff[4];
        #pragma unroll
        for (int b = 0; b < 4; b++) {
            int tx = min(max(ix0 + b - 1, 0), IMG_W - 1);
            coff[b] = tx * 12;
        }
        float a0 = 0.0f, a1 = 0.0f, a2 = 0.0f;
        #pragma unroll
        for (int a = 0; a < 4; a++) {
            int ty = min(max(iy0 + a - 1, 0), IMG_H - 1);
            const char* rowp = ibase + (unsigned)ty * ROW_BYTES;
            float r0 = 0.0f, r1 = 0.0f, r2 = 0.0f;
            #pragma unroll
            for (int b = 0; b < 4; b++) {
                const float* pp = (const float*)(rowp + coff[b]);
                float wv = wx[b];
                r0 = fmaf(wv, __ldg(pp + 0), r0);
                r1 = fmaf(wv, __ldg(pp + 1), r1);
                r2 = fmaf(wv, __ldg(pp + 2), r2);
            }
            a0 = fmaf(wy[a], r0, a0);
            a1 = fmaf(wy[a], r1, a1);
            a2 = fmaf(wy[a], r2, a2);
        }
        float* po = (float*)((char*)out + ((uint32_t)h * IMG_W + (uint32_t)w) * 12u);
        po[0] = a0; po[1] = a1; po[2] = a2;
    }
}

// Per-pixel gather from the staged smem tile (pattern broken but tile fits).
__device__ __noinline__ void smem_fallback(const float* __restrict__ wt,
                                           float* __restrict__ out,
                                           int row_lo, int col_lo,
                                           int w, int h0, float4 bxv) {
    for (int p = 0; p < PX; p++) {
        int h = h0 + p;
        float4 ryv = __ldg(&g_rdy4[h]);
        float4 rxv = __ldg(&g_rdx4[h]);
        float dy = ryv.x * bxv.x + ryv.y * bxv.y + ryv.z * bxv.z;
        float dx = rxv.x * bxv.x + rxv.y * bxv.y + rxv.z * bxv.z;
        float yy = (float)h + dy;
        float xx = (float)w + dx;
        float iy0f = floorf(yy), ix0f = floorf(xx);
        int   iy0 = (int)iy0f,   ix0 = (int)ix0f;
        float wy[4], wx[4];
        keys_weights(yy - iy0f, wy);
        keys_weights(xx - ix0f, wx);

        int sc[4];
        #pragma unroll
        for (int b = 0; b < 4; b++) {
            int tx = min(max(ix0 + b - 1, 0), IMG_W - 1);
            sc[b] = (tx - col_lo) * 3;
        }
        float a0 = 0.0f, a1 = 0.0f, a2 = 0.0f;
        #pragma unroll
        for (int a = 0; a < 4; a++) {
            int ty = min(max(iy0 + a - 1, 0), IMG_H - 1);
            const float* rowp = wt + (ty - row_lo) * TPITCH;
            float r0 = 0.0f, r1 = 0.0f, r2 = 0.0f;
            #pragma unroll
            for (int b = 0; b < 4; b++) {
                const float* pp = rowp + sc[b];
                float wv = wx[b];
                r0 = fmaf(wv, pp[0], r0);
                r1 = fmaf(wv, pp[1], r1);
                r2 = fmaf(wv, pp[2], r2);
            }
            a0 = fmaf(wy[a], r0, a0);
            a1 = fmaf(wy[a], r1, a1);
            a2 = fmaf(wy[a], r2, a2);
        }
        float* po = (float*)((char*)out + ((uint32_t)h * IMG_W + (uint32_t)w) * 12u);
        po[0] = a0; po[1] = a1; po[2] = a2;
    }
}

__global__ __launch_bounds__(NTHREADS, 6)
void elastic_warp_kernel(const float* __restrict__ img,
                         float* __restrict__ out) {
    __shared__ float    tile[WARPS_PER_BLOCK * TILE_F];   // 23232 B
    __shared__ uint64_t mbar[WARPS_PER_BLOCK];

    int w    = blockIdx.x * BX + threadIdx.x;
    int h0   = blockIdx.y * ROWS_PER_BLOCK + threadIdx.y * PX;
    int tid  = threadIdx.y * BX + threadIdx.x;
    int lane = tid & 31;
    int wid  = tid >> 5;

    if (tid < WARPS_PER_BLOCK) {
        uint32_t mb = smem_u32(&mbar[tid]);
        asm volatile("mbarrier.init.shared.b64 [%0], 1;" :: "r"(mb) : "memory");
    }
    asm volatile("fence.proxy.async.shared::cta;" ::: "memory");
    __syncthreads();

    float4 bxv = __ldg(&g_bx4[w]);

    // Edge warps (bottom remainder): guarded global path. h0 is warp-uniform.
    if (h0 + PX > IMG_H) {
        global_fallback(img, out, w, h0, bxv);
        return;
    }

    // Coordinates for all PX pixels; track pattern + true min/max.
    float fy[PX], fx[PX];
    int iy00 = 0, ix00 = 0;
    int tmin = 0, tmax = 0, cmn = 0, cmx = 0;
    bool quad = true;
    #pragma unroll
    for (int p = 0; p < PX; p++) {
        int h = h0 + p;
        float4 ryv = __ldg(&g_rdy4[h]);
        float4 rxv = __ldg(&g_rdx4[h]);
        float dy = ryv.x * bxv.x + ryv.y * bxv.y + ryv.z * bxv.z;
        float dx = rxv.x * bxv.x + rxv.y * bxv.y + rxv.z * bxv.z;
        float yy = (float)h + dy;
        float xx = (float)w + dx;
        float iy0f = floorf(yy), ix0f = floorf(xx);
        int   iy0 = (int)iy0f,   ix0 = (int)ix0f;
        fy[p] = yy - iy0f;
        fx[p] = xx - ix0f;
        if (p == 0) {
            iy00 = iy0; ix00 = ix0;
            tmin = iy0; tmax = iy0; cmn = ix0; cmx = ix0;
        } else {
            quad = quad && (ix0 == ix00) && (iy0 == iy00 + p);
            tmin = min(tmin, iy0); tmax = max(tmax, iy0);
            cmn  = min(cmn, ix0);  cmx  = max(cmx, ix0);
        }
    }

    int rminW = __reduce_min_sync(0xffffffffu, tmin);
    int rmaxW = __reduce_max_sync(0xffffffffu, tmax);
    int cminW = __reduce_min_sync(0xffffffffu, cmn);
    int cmaxW = __reduce_max_sync(0xffffffffu, cmx);

    bool stage_ok = (rmaxW - rminW <= TROWS - 4) && (cmaxW - cminW <= 37);
    if (!stage_ok) {
        global_fallback(img, out, w, h0, bxv);
        return;
    }

    int row_lo = min(max(rminW - 1, 0), IMG_H - 1);
    int col_lo = min(max(cminW - 1, 0) & ~3, COL_LO_MAX);

    float*   wt   = &tile[wid * TILE_F];
    uint32_t wt_u = smem_u32(wt);
    uint32_t mb_u = smem_u32(&mbar[wid]);

    // Stage TROWS x 528B via the bulk-copy engine.
    if (lane == 0) {
        asm volatile("mbarrier.arrive.expect_tx.shared.b64 _, [%0], %1;"
                     :: "r"(mb_u), "r"((uint32_t)STAGE_BYTES) : "memory");
        const char* ibase = (const char*)img;
        #pragma unroll
        for (int r = 0; r < TROWS; r++) {
            int gr = min(row_lo + r, IMG_H - 1);
            const char* src = ibase + (unsigned)gr * ROW_BYTES + (unsigned)col_lo * 12u;
            asm volatile("cp.async.bulk.shared::cta.global.mbarrier::complete_tx::bytes "
                         "[%0], [%1], %2, [%3];"
                         :: "r"(wt_u + (uint32_t)(r * TROW_BYTES)), "l"(src),
                            "r"((uint32_t)TROW_BYTES), "r"(mb_u) : "memory");
        }
    }

    bool warp_quad = __all_sync(0xffffffffu, quad);

    // Wait for the staged tile (acquire).
    {
        uint32_t done;
        asm volatile(
            "{\n\t.reg .pred p;\n\t"
            "mbarrier.try_wait.parity.acquire.cta.shared::cta.b64 p, [%1], 0;\n\t"
            "selp.b32 %0, 1, 0, p;\n\t}"
            : "=r"(done) : "r"(mb_u) : "memory");
        if (!done) {
            asm volatile(
                "{\n\t.reg .pred P1;\n\t"
                "W12_%=:\n\t"
                "mbarrier.try_wait.parity.acquire.cta.shared::cta.b64 P1, [%0], 0, 0x989680;\n\t"
                "@P1 bra.uni D12_%=;\n\t"
                "bra.uni W12_%=;\n\t"
                "D12_%=:\n\t}"
                :: "r"(mb_u) : "memory");
        }
    }

    if (!warp_quad) {
        smem_fallback(wt, out, row_lo, col_lo, w, h0, bxv);
        return;
    }

    // Fast path: staircase over PX+3 rows with 4-slot rolling activation.
    int sc[4];
    #pragma unroll
    for (int b = 0; b < 4; b++) {
        int tx = min(max(ix00 + b - 1, 0), IMG_W - 1);
        sc[b] = (tx - col_lo) * 3;
    }

    float wxA[4][4], wyA[4][4], acc[4][3];
    uint32_t obase = ((uint32_t)h0 * IMG_W + (uint32_t)w) * 12u;

    #pragma unroll
    for (int a = 0; a < PX + 3; a++) {
        // Activate pixel p = a.
        if (a < PX) {
            int s = a & 3;
            keys_weights(fx[a], wxA[s]);
            keys_weights(fy[a], wyA[s]);
            acc[s][0] = acc[s][1] = acc[s][2] = 0.0f;
        }
        int ty = min(max(iy00 + a - 1, 0), IMG_H - 1);
        const float* rowp = wt + (ty - row_lo) * TPITCH;
        float v[12];
        #pragma unroll
        for (int b = 0; b < 4; b++) {
            const float* p = rowp + sc[b];
            v[b * 3 + 0] = p[0];
            v[b * 3 + 1] = p[1];
            v[b * 3 + 2] = p[2];
        }
        #pragma unroll
        for (int p = 0; p < PX; p++) {
            int k = a - p;
            if (k >= 0 && k < 4) {
                int s = p & 3;
                const float* wxp = wxA[s];
                float r0 = wxp[0] * v[0];
                float r1 = wxp[0] * v[1];
                float r2 = wxp[0] * v[2];
                r0 = fmaf(wxp[1], v[3], r0);
                r1 = fmaf(wxp[1], v[4], r1);
                r2 = fmaf(wxp[1], v[5], r2);
                r0 = fmaf(wxp[2], v[6], r0);
                r1 = fmaf(wxp[2], v[7], r1);
                r2 = fmaf(wxp[2], v[8], r2);
                r0 = fmaf(wxp[3], v[9], r0);
                r1 = fmaf(wxp[3], v[10], r1);
                r2 = fmaf(wxp[3], v[11], r2);
                float wk = wyA[s][k];
                acc[s][0] = fmaf(wk, r0, acc[s][0]);
                acc[s][1] = fmaf(wk, r1, acc[s][1]);
                acc[s][2] = fmaf(wk, r2, acc[s][2]);
                if (k == 3) {   // pixel complete: store, slot frees next row
                    float* po = (float*)((char*)out + obase + (uint32_t)p * (IMG_W * 12u));
                    po[0] = acc[s][0];
                    po[1] = acc[s][1];
                    po[2] = acc[s][2];
                }
            }
        }
    }
}

extern "C" void kernel_launch(void* const* d_in, const int* in_sizes, int n_in,
                              void* d_out, int out_size) {
    const float* img   = (const float*)d_in[0];   // (2048, 4096, 3) fp32
    const float* dispc = (const float*)d_in[1];   // (2, 3, 3) fp32
    float*       out   = (float*)d_out;

    setup_tables<<<(IMG_W + 255) / 256, 256>>>(dispc);

    dim3 block(BX, BY, 1);
    dim3 grid(IMG_W / BX, (IMG_H + ROWS_PER_BLOCK - 1) / ROWS_PER_BLOCK, 1);
    elastic_warp_kernel<<<grid, block>>>(img, out);
}

// round 13
// speedup vs baseline: 1.2221x; 1.0252x over previous
#include <cuda_runtime.h>
#include <cuda_bf16.h>
#include <math.h>
#include <cstdint>

#define IMG_H 2048
#define IMG_W 4096
#define IMG_C 3
#define ROW_BYTES (IMG_W * IMG_C * 4)

#define BX 64
#define BY 2
#define NTHREADS (BX * BY)
#define WARPS_PER_BLOCK (NTHREADS / 32)
#define PX 8
#define ROWS_PER_BLOCK (BY * PX)           // 16 (2048 = 16 * 128, exact grid)

#define TROWS 14
#define TPITCH 132                          // floats per staged row = 528 B
#define TROW_BYTES (TPITCH * 4)             // 528
#define TILE_F (TROWS * TPITCH)
#define STAGE_BYTES (TROWS * TROW_BYTES)    // 7392
#define COL_LO_MAX 4052                     // col_lo*12 + 528 <= 49152

// Precomputed separable tables, float4-padded.
__device__ float4 g_bx4[IMG_W];
__device__ float4 g_rdy4[IMG_H];
__device__ float4 g_rdx4[IMG_H];

__device__ __forceinline__ uint32_t smem_u32(const void* p) {
    uint32_t a;
    asm("{ .reg .u64 t; cvta.to.shared.u64 t, %1; cvt.u32.u64 %0, t; }" : "=r"(a) : "l"(p));
    return a;
}

__device__ __forceinline__ float cubic_w(float t) {
    float at  = fabsf(t);
    float at2 = at * at;
    float at3 = at2 * at;
    const float a = -0.5f;
    float w_inner = (a + 2.0f) * at3 - (a + 3.0f) * at2 + 1.0f;
    float w_outer = a * at3 - 5.0f * a * at2 + 8.0f * a * at - 4.0f * a;
    return (at <= 1.0f) ? w_inner : ((at < 2.0f) ? w_outer : 0.0f);
}

__device__ __forceinline__ void ctrl_weights3(int i, float inv_scale, float w3[3]) {
    w3[0] = 0.0f; w3[1] = 0.0f; w3[2] = 0.0f;
    float u  = (float)i * inv_scale;
    int   i0 = (int)floorf(u);
    #pragma unroll
    for (int a = -1; a < 3; a++) {
        int   tap = i0 + a;
        float wv  = cubic_w(u - (float)tap);
        int   tc  = min(max(tap, 0), 2);
        w3[tc] += wv;
    }
}

__global__ void setup_tables(const float* __restrict__ dispc) {
    int i = blockIdx.x * blockDim.x + threadIdx.x;
    if (i < IMG_W) {
        float w3[3];
        ctrl_weights3(i, 2.0f / (float)(IMG_W - 1), w3);
        g_bx4[i] = make_float4(w3[0], w3[1], w3[2], 0.0f);
    }
    if (i < IMG_H) {
        float w3[3];
        ctrl_weights3(i, 2.0f / (float)(IMG_H - 1), w3);
        float ry[3], rx[3];
        #pragma unroll
        for (int x = 0; x < 3; x++) {
            ry[x] = 5.0f * (w3[0] * dispc[0 * 3 + x] + w3[1] * dispc[3 + x] + w3[2] * dispc[6 + x]);
            rx[x] = 5.0f * (w3[0] * dispc[9 + x]     + w3[1] * dispc[12 + x] + w3[2] * dispc[15 + x]);
        }
        g_rdy4[i] = make_float4(ry[0], ry[1], ry[2], 0.0f);
        g_rdx4[i] = make_float4(rx[0], rx[1], rx[2], 0.0f);
    }
}

__device__ __forceinline__ void keys_weights(float t, float w[4]) {
    float s  = 1.0f - t;
    float tt = t * t;
    float ss = s * s;
    w[0] = -0.5f * t * ss;
    w[1] = fmaf(fmaf(1.5f, t, -2.5f), tt, 1.0f);
    w[2] = fmaf(fmaf(1.5f, s, -2.5f), ss, 1.0f);
    w[3] = -0.5f * tt * s;
}

// Global per-pixel gather + store, h-guarded (unstageable warps).
__device__ __noinline__ void global_fallback(const float* __restrict__ img,
                                             float* __restrict__ out,
                                             int w, int h0, float4 bxv) {
    const char* ibase = (const char*)img;
    for (int p = 0; p < PX; p++) {
        int h = h0 + p;
        if (h >= IMG_H) break;
        float4 ryv = __ldg(&g_rdy4[h]);
        float4 rxv = __ldg(&g_rdx4[h]);
        float dy = ryv.x * bxv.x + ryv.y * bxv.y + ryv.z * bxv.z;
        float dx = rxv.x * bxv.x + rxv.y * bxv.y + rxv.z * bxv.z;
        float yy = (float)h + dy;
        float xx = (float)w + dx;
        float iy0f = floorf(yy), ix0f = floorf(xx);
        int   iy0 = (int)iy0f,   ix0 = (int)ix0f;
        float wy[4], wx[4];
        keys_weights(yy - iy0f, wy);
        keys_weights(xx - ix0f, wx);

        int coff[4];
        #pragma unroll
        for (int b = 0; b < 4; b++) {
            int tx = min(max(ix0 + b - 1, 0), IMG_W - 1);
            coff[b] = tx * 12;
        }
        float a0 = 0.0f, a1 = 0.0f, a2 = 0.0f;
        #pragma unroll
        for (int a = 0; a < 4; a++) {
            int ty = min(max(iy0 + a - 1, 0), IMG_H - 1);
            const char* rowp = ibase + (unsigned)ty * ROW_BYTES;
            float r0 = 0.0f, r1 = 0.0f, r2 = 0.0f;
            #pragma unroll
            for (int b = 0; b < 4; b++) {
                const float* pp = (const float*)(rowp + coff[b]);
                float wv = wx[b];
                r0 = fmaf(wv, __ldg(pp + 0), r0);
                r1 = fmaf(wv, __ldg(pp + 1), r1);
                r2 = fmaf(wv, __ldg(pp + 2), r2);
            }
            a0 = fmaf(wy[a], r0, a0);
            a1 = fmaf(wy[a], r1, a1);
            a2 = fmaf(wy[a], r2, a2);
        }
        float* po = (float*)((char*)out + ((uint32_t)h * IMG_W + (uint32_t)w) * 12u);
        po[0] = a0; po[1] = a1; po[2] = a2;
    }
}

// Per-pixel gather from the staged smem tile (pattern broken but tile fits).
__device__ __noinline__ void smem_fallback(const float* __restrict__ wt,
                                           float* __restrict__ out,
                                           int row_lo, int col_lo,
                                           int w, int h0, float4 bxv) {
    for (int p = 0; p < PX; p++) {
        int h = h0 + p;
        float4 ryv = __ldg(&g_rdy4[h]);
        float4 rxv = __ldg(&g_rdx4[h]);
        float dy = ryv.x * bxv.x + ryv.y * bxv.y + ryv.z * bxv.z;
        float dx = rxv.x * bxv.x + rxv.y * bxv.y + rxv.z * bxv.z;
        float yy = (float)h + dy;
        float xx = (float)w + dx;
        float iy0f = floorf(yy), ix0f = floorf(xx);
        int   iy0 = (int)iy0f,   ix0 = (int)ix0f;
        float wy[4], wx[4];
        keys_weights(yy - iy0f, wy);
        keys_weights(xx - ix0f, wx);

        int sc[4];
        #pragma unroll
        for (int b = 0; b < 4; b++) {
            int tx = min(max(ix0 + b - 1, 0), IMG_W - 1);
            sc[b] = (tx - col_lo) * 3;
        }
        float a0 = 0.0f, a1 = 0.0f, a2 = 0.0f;
        #pragma unroll
        for (int a = 0; a < 4; a++) {
            int ty = min(max(iy0 + a - 1, 0), IMG_H - 1);
            const float* rowp = wt + (ty - row_lo) * TPITCH;
            float r0 = 0.0f, r1 = 0.0f, r2 = 0.0f;
            #pragma unroll
            for (int b = 0; b < 4; b++) {
                const float* pp = rowp + sc[b];
                float wv = wx[b];
                r0 = fmaf(wv, pp[0], r0);
                r1 = fmaf(wv, pp[1], r1);
                r2 = fmaf(wv, pp[2], r2);
            }
            a0 = fmaf(wy[a], r0, a0);
            a1 = fmaf(wy[a], r1, a1);
            a2 = fmaf(wy[a], r2, a2);
        }
        float* po = (float*)((char*)out + ((uint32_t)h * IMG_W + (uint32_t)w) * 12u);
        po[0] = a0; po[1] = a1; po[2] = a2;
    }
}

__global__ __launch_bounds__(NTHREADS, 5)
void elastic_warp_kernel(const float* __restrict__ img,
                         float* __restrict__ out) {
    __shared__ float    tile[WARPS_PER_BLOCK * TILE_F];   // 4 * 7392 = 29568 B
    __shared__ uint64_t mbar[WARPS_PER_BLOCK];

    int w    = blockIdx.x * BX + threadIdx.x;
    int h0   = blockIdx.y * ROWS_PER_BLOCK + threadIdx.y * PX;
    int tid  = threadIdx.y * BX + threadIdx.x;
    int lane = tid & 31;
    int wid  = tid >> 5;

    if (tid < WARPS_PER_BLOCK) {
        uint32_t mb = smem_u32(&mbar[tid]);
        asm volatile("mbarrier.init.shared.b64 [%0], 1;" :: "r"(mb) : "memory");
    }
    asm volatile("fence.proxy.async.shared::cta;" ::: "memory");
    __syncthreads();

    float4 bxv = __ldg(&g_bx4[w]);

    // Coordinates for all PX pixels; track pattern + true min/max.
    float fy[PX], fx[PX];
    int iy00 = 0, ix00 = 0;
    int tmin = 0, tmax = 0, cmn = 0, cmx = 0;
    bool quad = true;
    #pragma unroll
    for (int p = 0; p < PX; p++) {
        int h = h0 + p;
        float4 ryv = __ldg(&g_rdy4[h]);
        float4 rxv = __ldg(&g_rdx4[h]);
        float dy = ryv.x * bxv.x + ryv.y * bxv.y + ryv.z * bxv.z;
        float dx = rxv.x * bxv.x + rxv.y * bxv.y + rxv.z * bxv.z;
        float yy = (float)h + dy;
        float xx = (float)w + dx;
        float iy0f = floorf(yy), ix0f = floorf(xx);
        int   iy0 = (int)iy0f,   ix0 = (int)ix0f;
        fy[p] = yy - iy0f;
        fx[p] = xx - ix0f;
        if (p == 0) {
            iy00 = iy0; ix00 = ix0;
            tmin = iy0; tmax = iy0; cmn = ix0; cmx = ix0;
        } else {
            quad = quad && (ix0 == ix00) && (iy0 == iy00 + p);
            tmin = min(tmin, iy0); tmax = max(tmax, iy0);
            cmn  = min(cmn, ix0);  cmx  = max(cmx, ix0);
        }
    }

    int rminW = __reduce_min_sync(0xffffffffu, tmin);
    int rmaxW = __reduce_max_sync(0xffffffffu, tmax);
    int cminW = __reduce_min_sync(0xffffffffu, cmn);
    int cmaxW = __reduce_max_sync(0xffffffffu, cmx);

    bool stage_ok = (rmaxW - rminW <= TROWS - 4) && (cmaxW - cminW <= 37);
    if (!stage_ok) {
        global_fallback(img, out, w, h0, bxv);
        return;
    }

    int row_lo = min(max(rminW - 1, 0), IMG_H - 1);
    int col_lo = min(max(cminW - 1, 0) & ~3, COL_LO_MAX);

    float*   wt   = &tile[wid * TILE_F];
    uint32_t wt_u = smem_u32(wt);
    uint32_t mb_u = smem_u32(&mbar[wid]);

    // Stage TROWS x 528B via the bulk-copy engine.
    if (lane == 0) {
        asm volatile("mbarrier.arrive.expect_tx.shared.b64 _, [%0], %1;"
                     :: "r"(mb_u), "r"((uint32_t)STAGE_BYTES) : "memory");
        const char* ibase = (const char*)img;
        #pragma unroll
        for (int r = 0; r < TROWS; r++) {
            int gr = min(row_lo + r, IMG_H - 1);
            const char* src = ibase + (unsigned)gr * ROW_BYTES + (unsigned)col_lo * 12u;
            asm volatile("cp.async.bulk.shared::cta.global.mbarrier::complete_tx::bytes "
                         "[%0], [%1], %2, [%3];"
                         :: "r"(wt_u + (uint32_t)(r * TROW_BYTES)), "l"(src),
                            "r"((uint32_t)TROW_BYTES), "r"(mb_u) : "memory");
        }
    }

    bool warp_quad = __all_sync(0xffffffffu, quad);

    // Wait for the staged tile (acquire).
    {
        uint32_t done;
        asm volatile(
            "{\n\t.reg .pred p;\n\t"
            "mbarrier.try_wait.parity.acquire.cta.shared::cta.b64 p, [%1], 0;\n\t"
            "selp.b32 %0, 1, 0, p;\n\t}"
            : "=r"(done) : "r"(mb_u) : "memory");
        if (!done) {
            asm volatile(
                "{\n\t.reg .pred P1;\n\t"
                "W13_%=:\n\t"
                "mbarrier.try_wait.parity.acquire.cta.shared::cta.b64 P1, [%0], 0, 0x989680;\n\t"
                "@P1 bra.uni D13_%=;\n\t"
                "bra.uni W13_%=;\n\t"
                "D13_%=:\n\t}"
                :: "r"(mb_u) : "memory");
        }
    }

    if (!warp_quad) {
        smem_fallback(wt, out, row_lo, col_lo, w, h0, bxv);
        return;
    }

    // Fast path: staircase over PX+3 rows with 4-slot rolling activation.
    int sc[4];
    #pragma unroll
    for (int b = 0; b < 4; b++) {
        int tx = min(max(ix00 + b - 1, 0), IMG_W - 1);
        sc[b] = (tx - col_lo) * 3;
    }

    float wxA[4][4], wyA[4][4], acc[4][3];
    uint32_t obase = ((uint32_t)h0 * IMG_W + (uint32_t)w) * 12u;

    #pragma unroll
    for (int a = 0; a < PX + 3; a++) {
        // Activate pixel p = a (weights only; acc initialized by k==0 MUL).
        if (a < PX) {
            int s = a & 3;
            keys_weights(fx[a], wxA[s]);
            keys_weights(fy[a], wyA[s]);
        }
        int ty = min(max(iy00 + a - 1, 0), IMG_H - 1);
        const float* rowp = wt + (ty - row_lo) * TPITCH;
        float v[12];
        #pragma unroll
        for (int b = 0; b < 4; b++) {
            const float* p = rowp + sc[b];
            v[b * 3 + 0] = p[0];
            v[b * 3 + 1] = p[1];
            v[b * 3 + 2] = p[2];
        }
        #pragma unroll
        for (int p = 0; p < PX; p++) {
            int k = a - p;
            if (k >= 0 && k < 4) {
                int s = p & 3;
                const float* wxp = wxA[s];
                float r0 = wxp[0] * v[0];
                float r1 = wxp[0] * v[1];
                float r2 = wxp[0] * v[2];
                r0 = fmaf(wxp[1], v[3], r0);
                r1 = fmaf(wxp[1], v[4], r1);
                r2 = fmaf(wxp[1], v[5], r2);
                r0 = fmaf(wxp[2], v[6], r0);
                r1 = fmaf(wxp[2], v[7], r1);
                r2 = fmaf(wxp[2], v[8], r2);
                r0 = fmaf(wxp[3], v[9], r0);
                r1 = fmaf(wxp[3], v[10], r1);
                r2 = fmaf(wxp[3], v[11], r2);
                float wk = wyA[s][k];
                if (k == 0) {     // first tap: overwrite (no zero-init needed)
                    acc[s][0] = wk * r0;
                    acc[s][1] = wk * r1;
                    acc[s][2] = wk * r2;
                } else {
                    acc[s][0] = fmaf(wk, r0, acc[s][0]);
                    acc[s][1] = fmaf(wk, r1, acc[s][1]);
                    acc[s][2] = fmaf(wk, r2, acc[s][2]);
                }
                if (k == 3) {     // pixel complete: store, slot frees next row
                    float* po = (float*)((char*)out + obase + (uint32_t)p * (IMG_W * 12u));
                    po[0] = acc[s][0];
                    po[1] = acc[s][1];
                    po[2] = acc[s][2];
                }
            }
        }
    }
}

extern "C" void kernel_launch(void* const* d_in, const int* in_sizes, int n_in,
                              void* d_out, int out_size) {
    const float* img   = (const float*)d_in[0];   // (2048, 4096, 3) fp32
    const float* dispc = (const float*)d_in[1];   // (2, 3, 3) fp32
    float*       out   = (float*)d_out;

    setup_tables<<<(IMG_W + 255) / 256, 256>>>(dispc);

    dim3 block(BX, BY, 1);
    dim3 grid(IMG_W / BX, IMG_H / ROWS_PER_BLOCK, 1);   // 2048 = 16 * 128, exact
    elastic_warp_kernel<<<grid, block>>>(img, out);
}